// round 9
// baseline (speedup 1.0000x reference)
#include <cuda_runtime.h>
#include <cuda_bf16.h>

// ----------------------------------------------------------------------------
// KB_Mapping_19361712570541 — mma.sync (HMMA) bf16 hi/lo split, 16-warp CTAs.
//   K1: t1 = relu(relu(dw1(x)) @ W1^T) [regs]; b2 = mask(relu(x@W2^T)+t1)
//   K2: b2p = relu(relu(dw2(b2)) @ W3^T)
//   K3: out = relu(x @ Wfa^T + b2p @ Wfb^T)
// GEMMs fp32-accurate via 3-term bf16 split: Ahi@Whi + Ahi@Wlo + Alo@Whi.
// Warp map (16 warps, 4x4): rw=warp&3 -> rows rw*32..+32 (2 m-tiles);
//                           cw=warp>>2 -> cols cw*32..+32 (2 n-pairs).
// ----------------------------------------------------------------------------

#define NTOK   131072
#define CCH    128
#define TILE_M 128
#define NTILES (NTOK / TILE_M)   // 1024
#define NT     512
#define PITCHB 136               // bf16 smem pitch (ldmatrix conflict-free)
#define WBYTES (CCH * PITCHB * 2)   // 34816 per bf16 matrix tile

typedef unsigned int u32;

// ---------------- device scratch ---------------------------------------------
__device__ float g_b2 [(size_t)NTOK * CCH];
__device__ float g_b2p[(size_t)NTOK * CCH];
__device__ __nv_bfloat16 g_whi[5][CCH * CCH];   // row-major [o][k] hi part
__device__ __nv_bfloat16 g_wlo[5][CCH * CCH];   // lo part

// ---------------- PTX helpers -------------------------------------------------
__device__ __forceinline__ u32 smem_u32(const void* p) {
    u32 a;
    asm("{ .reg .u64 t; cvta.to.shared.u64 t, %1; cvt.u32.u64 %0, t; }"
        : "=r"(a) : "l"(p));
    return a;
}
#define LDM4(r, a)                                                          \
    asm volatile("ldmatrix.sync.aligned.m8n8.x4.shared.b16 {%0,%1,%2,%3}, [%4];" \
                 : "=r"((r)[0]), "=r"((r)[1]), "=r"((r)[2]), "=r"((r)[3])   \
                 : "r"(a))
#define MMA(c, a, b0, b1)                                                   \
    asm volatile("mma.sync.aligned.m16n8k16.row.col.f32.bf16.bf16.f32 "     \
                 "{%0,%1,%2,%3}, {%4,%5,%6,%7}, {%8,%9}, {%0,%1,%2,%3};"    \
                 : "+f"((c)[0]), "+f"((c)[1]), "+f"((c)[2]), "+f"((c)[3])   \
                 : "r"((a)[0]), "r"((a)[1]), "r"((a)[2]), "r"((a)[3]),      \
                   "r"(b0), "r"(b1))

// ---------------- threefry-2x32 partitionable keep-bit (validated R5) ---------
__device__ __forceinline__ u32 rotl32(u32 x, int r) { return __funnelshift_l(x, x, r); }
__device__ __forceinline__ u32 keepbit(u32 fidx) {
    const u32 K0 = 0u, K1 = 42u, K2 = 0u ^ 42u ^ 0x1BD11BDAu;
    u32 x0 = 0u + K0;      // counts_hi = 0
    u32 x1 = fidx + K1;    // counts_lo = f
#define TF_R4(a,b,c,d)                               \
    x0 += x1; x1 = rotl32(x1,(a)); x1 ^= x0;         \
    x0 += x1; x1 = rotl32(x1,(b)); x1 ^= x0;         \
    x0 += x1; x1 = rotl32(x1,(c)); x1 ^= x0;         \
    x0 += x1; x1 = rotl32(x1,(d)); x1 ^= x0;
    TF_R4(13,15,26, 6);  x0 += K1; x1 += K2 + 1u;
    TF_R4(17,29,16,24);  x0 += K2; x1 += K0 + 2u;
    TF_R4(13,15,26, 6);  x0 += K0; x1 += K1 + 3u;
    TF_R4(17,29,16,24);  x0 += K1; x1 += K2 + 4u;
    TF_R4(13,15,26, 6);  x0 += K2; x1 += K0 + 5u;
#undef TF_R4
    return (~(x0 ^ x1)) >> 31;   // 1 = keep (MSB of xor-fold == 0)
}

// ---------------- weight prep: bf16 hi/lo split, row-major [o][k] ------------
__global__ void kPrep(const float* __restrict__ w1, const float* __restrict__ w2,
                      const float* __restrict__ w3, const float* __restrict__ wf) {
    int e = blockIdx.x * blockDim.x + threadIdx.x;
    if (e >= 5 * CCH * CCH) return;
    int mat = e >> 14, idx = e & 16383, o = idx >> 7, k = idx & 127;
    float v;
    if      (mat == 0) v = w1[idx];              // w_b1_pw
    else if (mat == 1) v = w2[idx];              // w_b2_1x1
    else if (mat == 2) v = w3[idx];              // w_b2_pw
    else if (mat == 3) v = wf[o * 256 + k];      // w_fusion[:, :128]
    else               v = wf[o * 256 + 128 + k];// w_fusion[:, 128:]
    __nv_bfloat16 h = __float2bfloat16(v);
    __nv_bfloat16 l = __float2bfloat16(v - __bfloat162float(h));
    g_whi[mat][idx] = h;
    g_wlo[mat][idx] = l;
}

// ---------------- tile helpers ------------------------------------------------
__device__ __forceinline__ void load8(float v[8], const float* __restrict__ p,
                                      long row, int k0) {
    if ((unsigned long)row < (unsigned long)NTOK) {
        float4 a = *(const float4*)(p + row * CCH + k0);
        float4 b = *(const float4*)(p + row * CCH + k0 + 4);
        v[0]=a.x; v[1]=a.y; v[2]=a.z; v[3]=a.w;
        v[4]=b.x; v[5]=b.y; v[6]=b.z; v[7]=b.w;
    } else {
#pragma unroll
        for (int j = 0; j < 8; j++) v[j] = 0.f;
    }
}

// Copy one pre-split weight matrix into pitched smem (hi+lo).
__device__ __forceinline__ void loadW(char* hd, char* ld, int mat, int tid) {
    const uint4* sh = (const uint4*)g_whi[mat];
    const uint4* sl = (const uint4*)g_wlo[mat];
#pragma unroll
    for (int q = tid; q < 2048; q += NT) {             // 16 uint4 per row
        int n = q >> 4, k0 = (q & 15) << 3;
        u32 doff = (u32)(n * PITCHB + k0) * 2;
        *(uint4*)(hd + doff) = sh[q];
        *(uint4*)(ld + doff) = sl[q];
    }
}

// Fill A tile (optionally fused 3-tap depthwise + relu) as bf16 hi/lo.
__device__ __forceinline__ void fillA(char* Ah, char* Al, const float* __restrict__ src,
                                      int base, const float* taps, int tid) {
#pragma unroll 1
    for (int q = tid; q < 2048; q += NT) {
        int m = q >> 4, k0 = (q & 15) << 3;
        long gr = (long)base + m;
        float v[8];
        if (taps) {
            float a[8], b[8], c[8];
            load8(a, src, gr - 1, k0);
            load8(b, src, gr,     k0);
            load8(c, src, gr + 1, k0);
#pragma unroll
            for (int j = 0; j < 8; j++) {
                int ch = k0 + j;
                v[j] = fmaxf(taps[ch] * a[j] + taps[CCH + ch] * b[j]
                             + taps[2 * CCH + ch] * c[j], 0.f);
            }
        } else {
            load8(v, src, gr, k0);
        }
        uint4 hv, lv;
        unsigned short* hp = (unsigned short*)&hv;
        unsigned short* lp = (unsigned short*)&lv;
#pragma unroll
        for (int j = 0; j < 8; j++) {
            __nv_bfloat16 h = __float2bfloat16(v[j]);
            __nv_bfloat16 l = __float2bfloat16(v[j] - __bfloat162float(h));
            hp[j] = *(unsigned short*)&h;
            lp[j] = *(unsigned short*)&l;
        }
        u32 off = (u32)(m * PITCHB + k0) * 2;
        *(uint4*)(Ah + off) = hv;
        *(uint4*)(Al + off) = lv;
    }
}

// 3-term split GEMM sweep: acc += Ahi@Whi + Ahi@Wlo + Alo@Whi.
// Warp: rows [m0, m0+32) (2 m-tiles) x cols [c0w, c0w+32) (2 n-pairs).
// acc[f][4], f = mt*4 + n8  (n8 in 0..3 => cols c0w + n8*8).
__device__ __forceinline__ void sweep(u32 ahs, u32 als, u32 whs, u32 wls,
                                      int m0, int c0w, int lane, float (*acc)[4]) {
    const u32 arow  = (u32)(m0 + (lane & 7) + (lane & 8));
    const u32 acolb = (u32)((lane & 16) >> 1);             // 0 or 8
    const u32 brow0 = (u32)((lane & 7) + ((lane & 16) >> 1));
    const u32 astride = (u32)(16 * PITCHB * 2);            // 16 rows of A
#pragma unroll 2
    for (int k = 0; k < 8; k++) {
        u32 aoff = (arow * PITCHB + (u32)k * 16 + acolb) * 2;
        u32 ah0[4], al0[4], ah1[4], al1[4];
        LDM4(ah0, ahs + aoff);
        LDM4(al0, als + aoff);
        LDM4(ah1, ahs + aoff + astride);
        LDM4(al1, als + aoff + astride);
        u32 bcol = ((u32)k * 16 + (u32)(lane & 8)) * 2;
        u32 boff0 = ((u32)c0w        + brow0) * (PITCHB * 2) + bcol;
        u32 boff1 = ((u32)(c0w + 16) + brow0) * (PITCHB * 2) + bcol;
        u32 bh0[4], bl0[4], bh1[4], bl1[4];
        LDM4(bh0, whs + boff0);
        LDM4(bl0, wls + boff0);
        LDM4(bh1, whs + boff1);
        LDM4(bl1, wls + boff1);
        // mtile 0, npair 0 -> acc[0], acc[1]
        MMA(acc[0], ah0, bh0[0], bh0[1]);
        MMA(acc[0], ah0, bl0[0], bl0[1]);
        MMA(acc[0], al0, bh0[0], bh0[1]);
        MMA(acc[1], ah0, bh0[2], bh0[3]);
        MMA(acc[1], ah0, bl0[2], bl0[3]);
        MMA(acc[1], al0, bh0[2], bh0[3]);
        // mtile 0, npair 1 -> acc[2], acc[3]
        MMA(acc[2], ah0, bh1[0], bh1[1]);
        MMA(acc[2], ah0, bl1[0], bl1[1]);
        MMA(acc[2], al0, bh1[0], bh1[1]);
        MMA(acc[3], ah0, bh1[2], bh1[3]);
        MMA(acc[3], ah0, bl1[2], bl1[3]);
        MMA(acc[3], al0, bh1[2], bh1[3]);
        // mtile 1, npair 0 -> acc[4], acc[5]
        MMA(acc[4], ah1, bh0[0], bh0[1]);
        MMA(acc[4], ah1, bl0[0], bl0[1]);
        MMA(acc[4], al1, bh0[0], bh0[1]);
        MMA(acc[5], ah1, bh0[2], bh0[3]);
        MMA(acc[5], ah1, bl0[2], bl0[3]);
        MMA(acc[5], al1, bh0[2], bh0[3]);
        // mtile 1, npair 1 -> acc[6], acc[7]
        MMA(acc[6], ah1, bh1[0], bh1[1]);
        MMA(acc[6], ah1, bl1[0], bl1[1]);
        MMA(acc[6], al1, bh1[0], bh1[1]);
        MMA(acc[7], ah1, bh1[2], bh1[3]);
        MMA(acc[7], ah1, bl1[2], bl1[3]);
        MMA(acc[7], al1, bh1[2], bh1[3]);
    }
}

#define ZACC(a) { _Pragma("unroll") for (int _i = 0; _i < 8; _i++) \
                  _Pragma("unroll") for (int _j = 0; _j < 4; _j++) (a)[_i][_j] = 0.f; }

// Shared-memory sizes
#define SM1 (6 * WBYTES + 3 * CCH * 4)   // W1 h/l, W2 h/l, A h/l, taps
#define SM2 (4 * WBYTES + 3 * CCH * 4)   // W3 h/l, A h/l, taps
#define SM3 (6 * WBYTES)                 // Wfa h/l, Wfb h/l, A h/l

// ---------------- K1: dw1 -> gemm W1 (regs); gemm W2; mask -> g_b2 -----------
__global__ void __launch_bounds__(NT)
K1(const float* __restrict__ x, const float* __restrict__ wdw) {
    extern __shared__ char sm[];
    char* W1h = sm;
    char* W1l = sm + WBYTES;
    char* W2h = sm + 2 * WBYTES;
    char* W2l = sm + 3 * WBYTES;
    char* Ah  = sm + 4 * WBYTES;
    char* Al  = sm + 5 * WBYTES;
    float* taps = (float*)(sm + 6 * WBYTES);

    const int tid = threadIdx.x, lane = tid & 31, warp = tid >> 5;
    const int base = blockIdx.x * TILE_M;
    const int m0 = (warp & 3) * 32, c0w = (warp >> 2) * 32;
    const int g = lane >> 2, t = lane & 3;

    loadW(W1h, W1l, 0, tid);
    loadW(W2h, W2l, 1, tid);
    for (int e = tid; e < 3 * CCH; e += NT)
        taps[e] = wdw[(e & 127) * 9 + (e >> 7) * 3 + 1];
    __syncthreads();

    // A = relu(dw1(x)); t1 partial = A @ W1^T (kept in registers)
    fillA(Ah, Al, x, base, taps, tid);
    __syncthreads();

    const u32 ahs = smem_u32(Ah), als = smem_u32(Al);
    float accT[8][4];
    ZACC(accT);
    sweep(ahs, als, smem_u32(W1h), smem_u32(W1l), m0, c0w, lane, accT);
    __syncthreads();   // all warps done reading A

    // refill A with plain x; accX = x @ W2^T
    fillA(Ah, Al, x, base, nullptr, tid);
    __syncthreads();

    float accX[8][4];
    ZACC(accX);
    sweep(ahs, als, smem_u32(W2h), smem_u32(W2l), m0, c0w, lane, accX);

    // b2 = mask(relu(accX) + relu(accT)) -> g_b2
#pragma unroll 1
    for (int f = 0; f < 8; f++) {
        const int mt = f >> 2, nt = f & 3;
        const int r0 = base + m0 + mt * 16 + g;
        const int c0 = c0w + nt * 8 + t * 2;
        float v00 = fmaxf(accX[f][0], 0.f) + fmaxf(accT[f][0], 0.f);
        float v01 = fmaxf(accX[f][1], 0.f) + fmaxf(accT[f][1], 0.f);
        float v10 = fmaxf(accX[f][2], 0.f) + fmaxf(accT[f][2], 0.f);
        float v11 = fmaxf(accX[f][3], 0.f) + fmaxf(accT[f][3], 0.f);
        u32 fc = (u32)c0 << 17;                 // flat = col*131072 + row
        if (!keepbit(fc + (u32)r0))                    v00 = 0.f;
        if (!keepbit(fc + (1u << 17) + (u32)r0))       v01 = 0.f;
        if (!keepbit(fc + (u32)(r0 + 8)))              v10 = 0.f;
        if (!keepbit(fc + (1u << 17) + (u32)(r0 + 8))) v11 = 0.f;
        *(float2*)(g_b2 + (size_t)r0 * CCH + c0)       = make_float2(v00, v01);
        *(float2*)(g_b2 + (size_t)(r0 + 8) * CCH + c0) = make_float2(v10, v11);
    }
}

// ---------------- K2: dw2(b2) -> gemm W3 -> relu -> g_b2p --------------------
__global__ void __launch_bounds__(NT)
K2(const float* __restrict__ wdw) {
    extern __shared__ char sm[];
    char* W3h = sm;
    char* W3l = sm + WBYTES;
    char* Ah  = sm + 2 * WBYTES;
    char* Al  = sm + 3 * WBYTES;
    float* taps = (float*)(sm + 4 * WBYTES);

    const int tid = threadIdx.x, lane = tid & 31, warp = tid >> 5;
    const int base = blockIdx.x * TILE_M;
    const int m0 = (warp & 3) * 32, c0w = (warp >> 2) * 32;
    const int g = lane >> 2, t = lane & 3;

    loadW(W3h, W3l, 2, tid);
    for (int e = tid; e < 3 * CCH; e += NT)
        taps[e] = wdw[(e & 127) * 9 + (e >> 7) * 3 + 1];
    __syncthreads();

    fillA(Ah, Al, g_b2, base, taps, tid);
    __syncthreads();

    float acc[8][4];
    ZACC(acc);
    sweep(smem_u32(Ah), smem_u32(Al), smem_u32(W3h), smem_u32(W3l), m0, c0w, lane, acc);

#pragma unroll
    for (int f = 0; f < 8; f++) {
        const int mt = f >> 2, nt = f & 3;
        const int r0 = base + m0 + mt * 16 + g;
        const int c0 = c0w + nt * 8 + t * 2;
        *(float2*)(g_b2p + (size_t)r0 * CCH + c0) =
            make_float2(fmaxf(acc[f][0], 0.f), fmaxf(acc[f][1], 0.f));
        *(float2*)(g_b2p + (size_t)(r0 + 8) * CCH + c0) =
            make_float2(fmaxf(acc[f][2], 0.f), fmaxf(acc[f][3], 0.f));
    }
}

// ---------------- K3: out = relu(x @ Wfa^T + b2p @ Wfb^T) --------------------
__global__ void __launch_bounds__(NT)
K3(const float* __restrict__ x, float* __restrict__ out) {
    extern __shared__ char sm[];
    char* Wah = sm;
    char* Wal = sm + WBYTES;
    char* Wbh = sm + 2 * WBYTES;
    char* Wbl = sm + 3 * WBYTES;
    char* Ah  = sm + 4 * WBYTES;
    char* Al  = sm + 5 * WBYTES;

    const int tid = threadIdx.x, lane = tid & 31, warp = tid >> 5;
    const int base = blockIdx.x * TILE_M;
    const int m0 = (warp & 3) * 32, c0w = (warp >> 2) * 32;
    const int g = lane >> 2, t = lane & 3;

    loadW(Wah, Wal, 3, tid);
    loadW(Wbh, Wbl, 4, tid);
    fillA(Ah, Al, x, base, nullptr, tid);
    __syncthreads();

    const u32 ahs = smem_u32(Ah), als = smem_u32(Al);
    float acc[8][4];
    ZACC(acc);
    sweep(ahs, als, smem_u32(Wah), smem_u32(Wal), m0, c0w, lane, acc);
    __syncthreads();

    fillA(Ah, Al, g_b2p, base, nullptr, tid);
    __syncthreads();
    sweep(ahs, als, smem_u32(Wbh), smem_u32(Wbl), m0, c0w, lane, acc);

#pragma unroll
    for (int f = 0; f < 8; f++) {
        const int mt = f >> 2, nt = f & 3;
        const int r0 = base + m0 + mt * 16 + g;
        const int c0 = c0w + nt * 8 + t * 2;
        *(float2*)(out + (size_t)r0 * CCH + c0) =
            make_float2(fmaxf(acc[f][0], 0.f), fmaxf(acc[f][1], 0.f));
        *(float2*)(out + (size_t)(r0 + 8) * CCH + c0) =
            make_float2(fmaxf(acc[f][2], 0.f), fmaxf(acc[f][3], 0.f));
    }
}

// ---------------- launch ------------------------------------------------------
extern "C" void kernel_launch(void* const* d_in, const int* in_sizes, int n_in,
                              void* d_out, int out_size) {
    const float* x        = (const float*)d_in[0];
    const float* w_b1_dw  = (const float*)d_in[1];
    const float* w_b1_pw  = (const float*)d_in[2];
    const float* w_b2_1x1 = (const float*)d_in[3];
    const float* w_b2_dw  = (const float*)d_in[4];
    const float* w_b2_pw  = (const float*)d_in[5];
    const float* w_fusion = (const float*)d_in[6];
    float*       out      = (float*)d_out;

    cudaFuncSetAttribute(K1, cudaFuncAttributeMaxDynamicSharedMemorySize, SM1);
    cudaFuncSetAttribute(K2, cudaFuncAttributeMaxDynamicSharedMemorySize, SM2);
    cudaFuncSetAttribute(K3, cudaFuncAttributeMaxDynamicSharedMemorySize, SM3);

    kPrep<<<(5 * CCH * CCH + 255) / 256, 256>>>(w_b1_pw, w_b2_1x1, w_b2_pw, w_fusion);
    K1<<<NTILES, NT, SM1>>>(x, w_b1_dw);
    K2<<<NTILES, NT, SM2>>>(w_b2_dw);
    K3<<<NTILES, NT, SM3>>>(x, out);
}

// round 12
// speedup vs baseline: 1.3169x; 1.3169x over previous
#include <cuda_runtime.h>
#include <cuda_fp16.h>

// ----------------------------------------------------------------------------
// KB_Mapping_19361712570541 — HMMA fp16 2-term split, persistent CTAs.
//   K1: t1 = relu(relu(dw1(x)) @ W1^T) [regs]; b2 = mask(relu(x@W2^T)+t1)
//   K2: b2p = relu(relu(dw2(b2)) @ W3^T)
//   K3: out = relu(x @ Wfa^T + b2p @ Wfb^T)
// GEMMs: A@W ~= Afp16 @ Whi + Afp16 @ Wlo   (W split to ~22 mantissa bits;
//   dropped Alo@W term ~2^-12 rel). All accumulation fp32.
// Warp map (16 warps, 4x4): rows (warp&3)*32..+32, cols (warp>>2)*32..+32.
// Persistent: each CTA loads weights once, loops tiles with grid stride.
// ----------------------------------------------------------------------------

#define NTOK   131072
#define CCH    128
#define TILE_M 128
#define NTILES (NTOK / TILE_M)   // 1024
#define NT     512
#define PITCHB 136               // fp16 smem pitch (ldmatrix conflict-free)
#define WBYTES (CCH * PITCHB * 2)   // 34816 bytes per fp16 matrix tile
#define GRID1  148
#define GRID2  296

typedef unsigned int u32;

// ---------------- device scratch ---------------------------------------------
__device__ float g_b2 [(size_t)NTOK * CCH];
__device__ float g_b2p[(size_t)NTOK * CCH];
__device__ __half g_whi[5][CCH * CCH];   // row-major [o][k] hi part
__device__ __half g_wlo[5][CCH * CCH];   // lo part (residual)

// ---------------- PTX helpers -------------------------------------------------
__device__ __forceinline__ u32 smem_u32(const void* p) {
    u32 a;
    asm("{ .reg .u64 t; cvta.to.shared.u64 t, %1; cvt.u32.u64 %0, t; }"
        : "=r"(a) : "l"(p));
    return a;
}
#define LDM4(r, a)                                                          \
    asm volatile("ldmatrix.sync.aligned.m8n8.x4.shared.b16 {%0,%1,%2,%3}, [%4];" \
                 : "=r"((r)[0]), "=r"((r)[1]), "=r"((r)[2]), "=r"((r)[3])   \
                 : "r"(a))
#define MMA(c, a, b0, b1)                                                   \
    asm volatile("mma.sync.aligned.m16n8k16.row.col.f32.f16.f16.f32 "       \
                 "{%0,%1,%2,%3}, {%4,%5,%6,%7}, {%8,%9}, {%0,%1,%2,%3};"    \
                 : "+f"((c)[0]), "+f"((c)[1]), "+f"((c)[2]), "+f"((c)[3])   \
                 : "r"((a)[0]), "r"((a)[1]), "r"((a)[2]), "r"((a)[3]),      \
                   "r"(b0), "r"(b1))

// ---------------- threefry-2x32 partitionable keep-bit (validated R5) ---------
__device__ __forceinline__ u32 rotl32(u32 x, int r) { return __funnelshift_l(x, x, r); }
__device__ __forceinline__ u32 keepbit(u32 fidx) {
    const u32 K0 = 0u, K1 = 42u, K2 = 0u ^ 42u ^ 0x1BD11BDAu;
    u32 x0 = 0u + K0;      // counts_hi = 0
    u32 x1 = fidx + K1;    // counts_lo = f
#define TF_R4(a,b,c,d)                               \
    x0 += x1; x1 = rotl32(x1,(a)); x1 ^= x0;         \
    x0 += x1; x1 = rotl32(x1,(b)); x1 ^= x0;         \
    x0 += x1; x1 = rotl32(x1,(c)); x1 ^= x0;         \
    x0 += x1; x1 = rotl32(x1,(d)); x1 ^= x0;
    TF_R4(13,15,26, 6);  x0 += K1; x1 += K2 + 1u;
    TF_R4(17,29,16,24);  x0 += K2; x1 += K0 + 2u;
    TF_R4(13,15,26, 6);  x0 += K0; x1 += K1 + 3u;
    TF_R4(17,29,16,24);  x0 += K1; x1 += K2 + 4u;
    TF_R4(13,15,26, 6);  x0 += K2; x1 += K0 + 5u;
#undef TF_R4
    return (~(x0 ^ x1)) >> 31;   // 1 = keep (MSB of xor-fold == 0)
}

// ---------------- weight prep: fp16 hi/lo split, row-major [o][k] ------------
__global__ void kPrep(const float* __restrict__ w1, const float* __restrict__ w2,
                      const float* __restrict__ w3, const float* __restrict__ wf) {
    int e = blockIdx.x * blockDim.x + threadIdx.x;
    if (e >= 5 * CCH * CCH) return;
    int mat = e >> 14, idx = e & 16383, o = idx >> 7, k = idx & 127;
    float v;
    if      (mat == 0) v = w1[idx];              // w_b1_pw
    else if (mat == 1) v = w2[idx];              // w_b2_1x1
    else if (mat == 2) v = w3[idx];              // w_b2_pw
    else if (mat == 3) v = wf[o * 256 + k];      // w_fusion[:, :128]
    else               v = wf[o * 256 + 128 + k];// w_fusion[:, 128:]
    __half h = __float2half_rn(v);
    __half l = __float2half_rn(v - __half2float(h));
    g_whi[mat][idx] = h;
    g_wlo[mat][idx] = l;
}

// ---------------- tile helpers ------------------------------------------------
__device__ __forceinline__ void load8(float v[8], const float* __restrict__ p,
                                      long row, int k0) {
    if ((unsigned long)row < (unsigned long)NTOK) {
        float4 a = *(const float4*)(p + row * CCH + k0);
        float4 b = *(const float4*)(p + row * CCH + k0 + 4);
        v[0]=a.x; v[1]=a.y; v[2]=a.z; v[3]=a.w;
        v[4]=b.x; v[5]=b.y; v[6]=b.z; v[7]=b.w;
    } else {
#pragma unroll
        for (int j = 0; j < 8; j++) v[j] = 0.f;
    }
}
__device__ __forceinline__ uint4 pack8h(const float v[8]) {
    uint4 r;
    unsigned short* s = (unsigned short*)&r;
#pragma unroll
    for (int j = 0; j < 8; j++) {
        __half h = __float2half_rn(v[j]);
        s[j] = *(unsigned short*)&h;
    }
    return r;
}

// Copy one pre-split weight matrix into pitched smem (hi+lo).
__device__ __forceinline__ void loadW(char* hd, char* ld, int mat, int tid) {
    const uint4* sh = (const uint4*)g_whi[mat];
    const uint4* sl = (const uint4*)g_wlo[mat];
#pragma unroll
    for (int q = tid; q < 2048; q += NT) {             // 16 uint4 per row
        int n = q >> 4, k0 = (q & 15) << 3;
        u32 doff = (u32)(n * PITCHB + k0) * 2;
        *(uint4*)(hd + doff) = sh[q];
        *(uint4*)(ld + doff) = sl[q];
    }
}

// Fill one A tile (optionally fused 3-tap depthwise + relu) as fp16.
__device__ __forceinline__ void fillA(char* A, const float* __restrict__ src,
                                      int base, const float* taps, int tid) {
#pragma unroll 1
    for (int q = tid; q < 2048; q += NT) {
        int m = q >> 4, k0 = (q & 15) << 3;
        long gr = (long)base + m;
        float v[8];
        if (taps) {
            float a[8], b[8], c[8];
            load8(a, src, gr - 1, k0);
            load8(b, src, gr,     k0);
            load8(c, src, gr + 1, k0);
#pragma unroll
            for (int j = 0; j < 8; j++) {
                int ch = k0 + j;
                v[j] = fmaxf(taps[ch] * a[j] + taps[CCH + ch] * b[j]
                             + taps[2 * CCH + ch] * c[j], 0.f);
            }
        } else {
            load8(v, src, gr, k0);
        }
        *(uint4*)(A + (u32)(m * PITCHB + k0) * 2) = pack8h(v);
    }
}

// K1 dual fill: A0 = fp16(relu(dw(x))), A1 = fp16(x); reads x rows once.
__device__ __forceinline__ void fillA_dual(char* A0, char* A1,
                                           const float* __restrict__ src,
                                           int base, const float* taps, int tid) {
#pragma unroll 1
    for (int q = tid; q < 2048; q += NT) {
        int m = q >> 4, k0 = (q & 15) << 3;
        long gr = (long)base + m;
        float a[8], b[8], c[8], v[8];
        load8(a, src, gr - 1, k0);
        load8(b, src, gr,     k0);
        load8(c, src, gr + 1, k0);
#pragma unroll
        for (int j = 0; j < 8; j++) {
            int ch = k0 + j;
            v[j] = fmaxf(taps[ch] * a[j] + taps[CCH + ch] * b[j]
                         + taps[2 * CCH + ch] * c[j], 0.f);
        }
        u32 off = (u32)(m * PITCHB + k0) * 2;
        *(uint4*)(A0 + off) = pack8h(v);
        *(uint4*)(A1 + off) = pack8h(b);
    }
}

// 2-term split GEMM sweep: acc += A @ Whi + A @ Wlo.
// Warp: rows [m0, m0+32) (2 m-tiles) x cols [c0w, c0w+32) (2 n-pairs).
__device__ __forceinline__ void sweep(u32 as, u32 whs, u32 wls,
                                      int m0, int c0w, int lane, float (*acc)[4]) {
    const u32 arow  = (u32)(m0 + (lane & 7) + (lane & 8));
    const u32 acolb = (u32)((lane & 16) >> 1);             // 0 or 8
    const u32 brow0 = (u32)((lane & 7) + ((lane & 16) >> 1));
    const u32 astride = (u32)(16 * PITCHB * 2);            // 16 rows of A
#pragma unroll 2
    for (int k = 0; k < 8; k++) {
        u32 aoff = (arow * PITCHB + (u32)k * 16 + acolb) * 2;
        u32 a0[4], a1[4];
        LDM4(a0, as + aoff);
        LDM4(a1, as + aoff + astride);
        u32 bcol = ((u32)k * 16 + (u32)(lane & 8)) * 2;
        u32 boff0 = ((u32)c0w        + brow0) * (PITCHB * 2) + bcol;
        u32 boff1 = ((u32)(c0w + 16) + brow0) * (PITCHB * 2) + bcol;
        u32 bh0[4], bl0[4], bh1[4], bl1[4];
        LDM4(bh0, whs + boff0);
        LDM4(bl0, wls + boff0);
        LDM4(bh1, whs + boff1);
        LDM4(bl1, wls + boff1);
        MMA(acc[0], a0, bh0[0], bh0[1]);
        MMA(acc[0], a0, bl0[0], bl0[1]);
        MMA(acc[1], a0, bh0[2], bh0[3]);
        MMA(acc[1], a0, bl0[2], bl0[3]);
        MMA(acc[2], a0, bh1[0], bh1[1]);
        MMA(acc[2], a0, bl1[0], bl1[1]);
        MMA(acc[3], a0, bh1[2], bh1[3]);
        MMA(acc[3], a0, bl1[2], bl1[3]);
        MMA(acc[4], a1, bh0[0], bh0[1]);
        MMA(acc[4], a1, bl0[0], bl0[1]);
        MMA(acc[5], a1, bh0[2], bh0[3]);
        MMA(acc[5], a1, bl0[2], bl0[3]);
        MMA(acc[6], a1, bh1[0], bh1[1]);
        MMA(acc[6], a1, bl1[0], bl1[1]);
        MMA(acc[7], a1, bh1[2], bh1[3]);
        MMA(acc[7], a1, bl1[2], bl1[3]);
    }
}

#define ZACC(a) { _Pragma("unroll") for (int _i = 0; _i < 8; _i++) \
                  _Pragma("unroll") for (int _j = 0; _j < 4; _j++) (a)[_i][_j] = 0.f; }

// Shared-memory sizes
#define SM1 (6 * WBYTES + 3 * CCH * 4)   // W1 h/l, W2 h/l, A0, A1, taps
#define SM2 (3 * WBYTES + 3 * CCH * 4)   // W3 h/l, A, taps
#define SM3 (6 * WBYTES)                 // Wfa h/l, Wfb h/l, A0, A1

// ---------------- K1: dw1 -> gemm W1 (regs); gemm W2; mask -> g_b2 -----------
__global__ void __launch_bounds__(NT)
K1(const float* __restrict__ x, const float* __restrict__ wdw) {
    extern __shared__ char sm[];
    char* W1h = sm;
    char* W1l = sm + WBYTES;
    char* W2h = sm + 2 * WBYTES;
    char* W2l = sm + 3 * WBYTES;
    char* A0  = sm + 4 * WBYTES;
    char* A1  = sm + 5 * WBYTES;
    float* taps = (float*)(sm + 6 * WBYTES);

    const int tid = threadIdx.x, lane = tid & 31, warp = tid >> 5;
    const int m0 = (warp & 3) * 32, c0w = (warp >> 2) * 32;
    const int g = lane >> 2, t = lane & 3;

    loadW(W1h, W1l, 0, tid);
    loadW(W2h, W2l, 1, tid);
    for (int e = tid; e < 3 * CCH; e += NT)
        taps[e] = wdw[(e & 127) * 9 + (e >> 7) * 3 + 1];

    const u32 a0s = smem_u32(A0), a1s = smem_u32(A1);
    const u32 w1hs = smem_u32(W1h), w1ls = smem_u32(W1l);
    const u32 w2hs = smem_u32(W2h), w2ls = smem_u32(W2l);

    for (int tile = blockIdx.x; tile < NTILES; tile += gridDim.x) {
        const int base = tile * TILE_M;
        fillA_dual(A0, A1, x, base, taps, tid);
        __syncthreads();

        float accT[8][4], accX[8][4];
        ZACC(accT); ZACC(accX);
        sweep(a0s, w1hs, w1ls, m0, c0w, lane, accT);
        sweep(a1s, w2hs, w2ls, m0, c0w, lane, accX);

        // b2 = mask(relu(accX) + relu(accT)) -> g_b2
#pragma unroll 1
        for (int f = 0; f < 8; f++) {
            const int mt = f >> 2, nt = f & 3;
            const int r0 = base + m0 + mt * 16 + g;
            const int c0 = c0w + nt * 8 + t * 2;
            float v00 = fmaxf(accX[f][0], 0.f) + fmaxf(accT[f][0], 0.f);
            float v01 = fmaxf(accX[f][1], 0.f) + fmaxf(accT[f][1], 0.f);
            float v10 = fmaxf(accX[f][2], 0.f) + fmaxf(accT[f][2], 0.f);
            float v11 = fmaxf(accX[f][3], 0.f) + fmaxf(accT[f][3], 0.f);
            u32 fc = (u32)c0 << 17;             // flat = col*131072 + row
            if (!keepbit(fc + (u32)r0))                    v00 = 0.f;
            if (!keepbit(fc + (1u << 17) + (u32)r0))       v01 = 0.f;
            if (!keepbit(fc + (u32)(r0 + 8)))              v10 = 0.f;
            if (!keepbit(fc + (1u << 17) + (u32)(r0 + 8))) v11 = 0.f;
            *(float2*)(g_b2 + (size_t)r0 * CCH + c0)       = make_float2(v00, v01);
            *(float2*)(g_b2 + (size_t)(r0 + 8) * CCH + c0) = make_float2(v10, v11);
        }
        __syncthreads();   // A buffers reused next iteration
    }
}

// ---------------- K2: dw2(b2) -> gemm W3 -> relu -> g_b2p --------------------
__global__ void __launch_bounds__(NT)
K2(const float* __restrict__ wdw) {
    extern __shared__ char sm[];
    char* W3h = sm;
    char* W3l = sm + WBYTES;
    char* A   = sm + 2 * WBYTES;
    float* taps = (float*)(sm + 3 * WBYTES);

    const int tid = threadIdx.x, lane = tid & 31, warp = tid >> 5;
    const int m0 = (warp & 3) * 32, c0w = (warp >> 2) * 32;
    const int g = lane >> 2, t = lane & 3;

    loadW(W3h, W3l, 2, tid);
    for (int e = tid; e < 3 * CCH; e += NT)
        taps[e] = wdw[(e & 127) * 9 + (e >> 7) * 3 + 1];

    const u32 as = smem_u32(A);
    const u32 whs = smem_u32(W3h), wls = smem_u32(W3l);

    for (int tile = blockIdx.x; tile < NTILES; tile += gridDim.x) {
        const int base = tile * TILE_M;
        fillA(A, g_b2, base, taps, tid);
        __syncthreads();

        float acc[8][4];
        ZACC(acc);
        sweep(as, whs, wls, m0, c0w, lane, acc);

#pragma unroll
        for (int f = 0; f < 8; f++) {
            const int mt = f >> 2, nt = f & 3;
            const int r0 = base + m0 + mt * 16 + g;
            const int c0 = c0w + nt * 8 + t * 2;
            *(float2*)(g_b2p + (size_t)r0 * CCH + c0) =
                make_float2(fmaxf(acc[f][0], 0.f), fmaxf(acc[f][1], 0.f));
            *(float2*)(g_b2p + (size_t)(r0 + 8) * CCH + c0) =
                make_float2(fmaxf(acc[f][2], 0.f), fmaxf(acc[f][3], 0.f));
        }
        __syncthreads();
    }
}

// ---------------- K3: out = relu(x @ Wfa^T + b2p @ Wfb^T) --------------------
__global__ void __launch_bounds__(NT)
K3(const float* __restrict__ x, float* __restrict__ out) {
    extern __shared__ char sm[];
    char* Wah = sm;
    char* Wal = sm + WBYTES;
    char* Wbh = sm + 2 * WBYTES;
    char* Wbl = sm + 3 * WBYTES;
    char* A0  = sm + 4 * WBYTES;
    char* A1  = sm + 5 * WBYTES;

    const int tid = threadIdx.x, lane = tid & 31, warp = tid >> 5;
    const int m0 = (warp & 3) * 32, c0w = (warp >> 2) * 32;
    const int g = lane >> 2, t = lane & 3;

    loadW(Wah, Wal, 3, tid);
    loadW(Wbh, Wbl, 4, tid);

    const u32 a0s = smem_u32(A0), a1s = smem_u32(A1);
    const u32 wahs = smem_u32(Wah), wals = smem_u32(Wal);
    const u32 wbhs = smem_u32(Wbh), wbls = smem_u32(Wbl);

    for (int tile = blockIdx.x; tile < NTILES; tile += gridDim.x) {
        const int base = tile * TILE_M;
        fillA(A0, x,     base, nullptr, tid);
        fillA(A1, g_b2p, base, nullptr, tid);
        __syncthreads();

        float acc[8][4];
        ZACC(acc);
        sweep(a0s, wahs, wals, m0, c0w, lane, acc);
        sweep(a1s, wbhs, wbls, m0, c0w, lane, acc);

#pragma unroll
        for (int f = 0; f < 8; f++) {
            const int mt = f >> 2, nt = f & 3;
            const int r0 = base + m0 + mt * 16 + g;
            const int c0 = c0w + nt * 8 + t * 2;
            *(float2*)(out + (size_t)r0 * CCH + c0) =
                make_float2(fmaxf(acc[f][0], 0.f), fmaxf(acc[f][1], 0.f));
            *(float2*)(out + (size_t)(r0 + 8) * CCH + c0) =
                make_float2(fmaxf(acc[f][2], 0.f), fmaxf(acc[f][3], 0.f));
        }
        __syncthreads();
    }
}

// ---------------- launch ------------------------------------------------------
extern "C" void kernel_launch(void* const* d_in, const int* in_sizes, int n_in,
                              void* d_out, int out_size) {
    const float* x        = (const float*)d_in[0];
    const float* w_b1_dw  = (const float*)d_in[1];
    const float* w_b1_pw  = (const float*)d_in[2];
    const float* w_b2_1x1 = (const float*)d_in[3];
    const float* w_b2_dw  = (const float*)d_in[4];
    const float* w_b2_pw  = (const float*)d_in[5];
    const float* w_fusion = (const float*)d_in[6];
    float*       out      = (float*)d_out;

    cudaFuncSetAttribute(K1, cudaFuncAttributeMaxDynamicSharedMemorySize, SM1);
    cudaFuncSetAttribute(K2, cudaFuncAttributeMaxDynamicSharedMemorySize, SM2);
    cudaFuncSetAttribute(K3, cudaFuncAttributeMaxDynamicSharedMemorySize, SM3);

    kPrep<<<(5 * CCH * CCH + 255) / 256, 256>>>(w_b1_pw, w_b2_1x1, w_b2_pw, w_fusion);
    K1<<<GRID1, NT, SM1>>>(x, w_b1_dw);
    K2<<<GRID2, NT, SM2>>>(w_b2_dw);
    K3<<<GRID1, NT, SM3>>>(x, out);
}

// round 13
// speedup vs baseline: 1.5224x; 1.1561x over previous
#include <cuda_runtime.h>
#include <cuda_fp16.h>

// ----------------------------------------------------------------------------
// KB_Mapping_19361712570541 — HMMA fp16 2-term split, persistent CTAs,
// fp16 intermediates, K3 register-prefetch pipeline.
//   K1: t1 = relu(relu(dw1(x)) @ W1^T) [regs]; b2 = mask(relu(x@W2^T)+t1)
//       -> g_b2h (fp16); side-writes g_xh = fp16(x).
//   K2: b2p = relu(relu(dw2(b2h)) @ W3^T) -> g_b2ph (fp16)
//   K3: out = relu(xh @ Wfa^T + b2ph @ Wfb^T)   (raw fp16 tile copies)
// GEMMs: A@W ~= Afp16 @ Whi + Afp16 @ Wlo  (W split ~22 mantissa bits).
// Warp map (16 warps, 4x4): rows (warp&3)*32..+32, cols (warp>>2)*32..+32.
// ----------------------------------------------------------------------------

#define NTOK   131072
#define CCH    128
#define TILE_M 128
#define NTILES (NTOK / TILE_M)   // 1024
#define NT     512
#define PITCHB 136               // fp16 smem pitch (ldmatrix conflict-free)
#define WBYTES (CCH * PITCHB * 2)   // 34816 bytes per fp16 matrix tile
#define GRID1  148
#define GRID2  296

typedef unsigned int u32;

// ---------------- device scratch ---------------------------------------------
__device__ __half g_xh  [(size_t)NTOK * CCH];   // fp16(x), written by K1
__device__ __half g_b2h [(size_t)NTOK * CCH];   // fp16(b2)
__device__ __half g_b2ph[(size_t)NTOK * CCH];   // fp16(b2p)
__device__ __half g_whi[5][CCH * CCH];          // row-major [o][k] hi part
__device__ __half g_wlo[5][CCH * CCH];          // lo part (residual)

// ---------------- PTX helpers -------------------------------------------------
__device__ __forceinline__ u32 smem_u32(const void* p) {
    u32 a;
    asm("{ .reg .u64 t; cvta.to.shared.u64 t, %1; cvt.u32.u64 %0, t; }"
        : "=r"(a) : "l"(p));
    return a;
}
#define LDM4(r, a)                                                          \
    asm volatile("ldmatrix.sync.aligned.m8n8.x4.shared.b16 {%0,%1,%2,%3}, [%4];" \
                 : "=r"((r)[0]), "=r"((r)[1]), "=r"((r)[2]), "=r"((r)[3])   \
                 : "r"(a))
#define MMA(c, a, b0, b1)                                                   \
    asm volatile("mma.sync.aligned.m16n8k16.row.col.f32.f16.f16.f32 "       \
                 "{%0,%1,%2,%3}, {%4,%5,%6,%7}, {%8,%9}, {%0,%1,%2,%3};"    \
                 : "+f"((c)[0]), "+f"((c)[1]), "+f"((c)[2]), "+f"((c)[3])   \
                 : "r"((a)[0]), "r"((a)[1]), "r"((a)[2]), "r"((a)[3]),      \
                   "r"(b0), "r"(b1))

// ---------------- threefry-2x32 partitionable keep-bit (validated R5) ---------
__device__ __forceinline__ u32 rotl32(u32 x, int r) { return __funnelshift_l(x, x, r); }
__device__ __forceinline__ u32 keepbit(u32 fidx) {
    const u32 K0 = 0u, K1 = 42u, K2 = 0u ^ 42u ^ 0x1BD11BDAu;
    u32 x0 = 0u + K0;      // counts_hi = 0
    u32 x1 = fidx + K1;    // counts_lo = f
#define TF_R4(a,b,c,d)                               \
    x0 += x1; x1 = rotl32(x1,(a)); x1 ^= x0;         \
    x0 += x1; x1 = rotl32(x1,(b)); x1 ^= x0;         \
    x0 += x1; x1 = rotl32(x1,(c)); x1 ^= x0;         \
    x0 += x1; x1 = rotl32(x1,(d)); x1 ^= x0;
    TF_R4(13,15,26, 6);  x0 += K1; x1 += K2 + 1u;
    TF_R4(17,29,16,24);  x0 += K2; x1 += K0 + 2u;
    TF_R4(13,15,26, 6);  x0 += K0; x1 += K1 + 3u;
    TF_R4(17,29,16,24);  x0 += K1; x1 += K2 + 4u;
    TF_R4(13,15,26, 6);  x0 += K2; x1 += K0 + 5u;
#undef TF_R4
    return (~(x0 ^ x1)) >> 31;   // 1 = keep (MSB of xor-fold == 0)
}

// ---------------- weight prep: fp16 hi/lo split, row-major [o][k] ------------
__global__ void kPrep(const float* __restrict__ w1, const float* __restrict__ w2,
                      const float* __restrict__ w3, const float* __restrict__ wf) {
    int e = blockIdx.x * blockDim.x + threadIdx.x;
    if (e >= 5 * CCH * CCH) return;
    int mat = e >> 14, idx = e & 16383, o = idx >> 7, k = idx & 127;
    float v;
    if      (mat == 0) v = w1[idx];              // w_b1_pw
    else if (mat == 1) v = w2[idx];              // w_b2_1x1
    else if (mat == 2) v = w3[idx];              // w_b2_pw
    else if (mat == 3) v = wf[o * 256 + k];      // w_fusion[:, :128]
    else               v = wf[o * 256 + 128 + k];// w_fusion[:, 128:]
    __half h = __float2half_rn(v);
    __half l = __float2half_rn(v - __half2float(h));
    g_whi[mat][idx] = h;
    g_wlo[mat][idx] = l;
}

// ---------------- tile helpers ------------------------------------------------
__device__ __forceinline__ void load8(float v[8], const float* __restrict__ p,
                                      long row, int k0) {
    if ((unsigned long)row < (unsigned long)NTOK) {
        float4 a = *(const float4*)(p + row * CCH + k0);
        float4 b = *(const float4*)(p + row * CCH + k0 + 4);
        v[0]=a.x; v[1]=a.y; v[2]=a.z; v[3]=a.w;
        v[4]=b.x; v[5]=b.y; v[6]=b.z; v[7]=b.w;
    } else {
#pragma unroll
        for (int j = 0; j < 8; j++) v[j] = 0.f;
    }
}
__device__ __forceinline__ void load8h(float v[8], const __half* __restrict__ p,
                                       long row, int k0) {
    if ((unsigned long)row < (unsigned long)NTOK) {
        uint4 r = *(const uint4*)(p + row * CCH + k0);
        const __half2* h2 = (const __half2*)&r;
#pragma unroll
        for (int j = 0; j < 4; j++) {
            float2 f = __half22float2(h2[j]);
            v[2 * j] = f.x; v[2 * j + 1] = f.y;
        }
    } else {
#pragma unroll
        for (int j = 0; j < 8; j++) v[j] = 0.f;
    }
}
__device__ __forceinline__ uint4 pack8h(const float v[8]) {
    uint4 r;
    __half2* h2 = (__half2*)&r;
#pragma unroll
    for (int j = 0; j < 4; j++)
        h2[j] = __floats2half2_rn(v[2 * j], v[2 * j + 1]);
    return r;
}

// Copy one pre-split weight matrix into pitched smem (hi+lo).
__device__ __forceinline__ void loadW(char* hd, char* ld, int mat, int tid) {
    const uint4* sh = (const uint4*)g_whi[mat];
    const uint4* sl = (const uint4*)g_wlo[mat];
#pragma unroll
    for (int q = tid; q < 2048; q += NT) {             // 16 uint4 per row
        int n = q >> 4, k0 = (q & 15) << 3;
        u32 doff = (u32)(n * PITCHB + k0) * 2;
        *(uint4*)(hd + doff) = sh[q];
        *(uint4*)(ld + doff) = sl[q];
    }
}

// K1 dual fill from fp32 x: A0 = fp16(relu(dw(x))), A1 = fp16(x); also
// side-writes g_xh = fp16(x) for K3.
__device__ __forceinline__ void fillA_dual(char* A0, char* A1,
                                           const float* __restrict__ src,
                                           int base, const float* taps, int tid) {
#pragma unroll 1
    for (int q = tid; q < 2048; q += NT) {
        int m = q >> 4, k0 = (q & 15) << 3;
        long gr = (long)base + m;
        float a[8], b[8], c[8], v[8];
        load8(a, src, gr - 1, k0);
        load8(b, src, gr,     k0);
        load8(c, src, gr + 1, k0);
#pragma unroll
        for (int j = 0; j < 8; j++) {
            int ch = k0 + j;
            v[j] = fmaxf(taps[ch] * a[j] + taps[CCH + ch] * b[j]
                         + taps[2 * CCH + ch] * c[j], 0.f);
        }
        u32 off = (u32)(m * PITCHB + k0) * 2;
        uint4 xb = pack8h(b);
        *(uint4*)(A0 + off) = pack8h(v);
        *(uint4*)(A1 + off) = xb;
        *(uint4*)(g_xh + (size_t)gr * CCH + k0) = xb;
    }
}

// K2 fill from fp16 source with fused dw + relu.
__device__ __forceinline__ void fillA_h(char* A, const __half* __restrict__ src,
                                        int base, const float* taps, int tid) {
#pragma unroll 1
    for (int q = tid; q < 2048; q += NT) {
        int m = q >> 4, k0 = (q & 15) << 3;
        long gr = (long)base + m;
        float a[8], b[8], c[8], v[8];
        load8h(a, src, gr - 1, k0);
        load8h(b, src, gr,     k0);
        load8h(c, src, gr + 1, k0);
#pragma unroll
        for (int j = 0; j < 8; j++) {
            int ch = k0 + j;
            v[j] = fmaxf(taps[ch] * a[j] + taps[CCH + ch] * b[j]
                         + taps[2 * CCH + ch] * c[j], 0.f);
        }
        *(uint4*)(A + (u32)(m * PITCHB + k0) * 2) = pack8h(v);
    }
}

// 2-term split GEMM sweep: acc += A @ Whi + A @ Wlo.
// Warp: rows [m0, m0+32) (2 m-tiles) x cols [c0w, c0w+32) (2 n-pairs).
__device__ __forceinline__ void sweep(u32 as, u32 whs, u32 wls,
                                      int m0, int c0w, int lane, float (*acc)[4]) {
    const u32 arow  = (u32)(m0 + (lane & 7) + (lane & 8));
    const u32 acolb = (u32)((lane & 16) >> 1);             // 0 or 8
    const u32 brow0 = (u32)((lane & 7) + ((lane & 16) >> 1));
    const u32 astride = (u32)(16 * PITCHB * 2);            // 16 rows of A
#pragma unroll 2
    for (int k = 0; k < 8; k++) {
        u32 aoff = (arow * PITCHB + (u32)k * 16 + acolb) * 2;
        u32 a0[4], a1[4];
        LDM4(a0, as + aoff);
        LDM4(a1, as + aoff + astride);
        u32 bcol = ((u32)k * 16 + (u32)(lane & 8)) * 2;
        u32 boff0 = ((u32)c0w        + brow0) * (PITCHB * 2) + bcol;
        u32 boff1 = ((u32)(c0w + 16) + brow0) * (PITCHB * 2) + bcol;
        u32 bh0[4], bl0[4], bh1[4], bl1[4];
        LDM4(bh0, whs + boff0);
        LDM4(bl0, wls + boff0);
        LDM4(bh1, whs + boff1);
        LDM4(bl1, wls + boff1);
        MMA(acc[0], a0, bh0[0], bh0[1]);
        MMA(acc[0], a0, bl0[0], bl0[1]);
        MMA(acc[1], a0, bh0[2], bh0[3]);
        MMA(acc[1], a0, bl0[2], bl0[3]);
        MMA(acc[2], a0, bh1[0], bh1[1]);
        MMA(acc[2], a0, bl1[0], bl1[1]);
        MMA(acc[3], a0, bh1[2], bh1[3]);
        MMA(acc[3], a0, bl1[2], bl1[3]);
        MMA(acc[4], a1, bh0[0], bh0[1]);
        MMA(acc[4], a1, bl0[0], bl0[1]);
        MMA(acc[5], a1, bh0[2], bh0[3]);
        MMA(acc[5], a1, bl0[2], bl0[3]);
        MMA(acc[6], a1, bh1[0], bh1[1]);
        MMA(acc[6], a1, bl1[0], bl1[1]);
        MMA(acc[7], a1, bh1[2], bh1[3]);
        MMA(acc[7], a1, bl1[2], bl1[3]);
    }
}

#define ZACC(a) { _Pragma("unroll") for (int _i = 0; _i < 8; _i++) \
                  _Pragma("unroll") for (int _j = 0; _j < 4; _j++) (a)[_i][_j] = 0.f; }

// Shared-memory sizes
#define SM1 (6 * WBYTES + 3 * CCH * 4)   // W1 h/l, W2 h/l, A0, A1, taps
#define SM2 (3 * WBYTES + 3 * CCH * 4)   // W3 h/l, A, taps
#define SM3 (6 * WBYTES)                 // Wfa h/l, Wfb h/l, A0, A1

// ---------------- K1: dw1 -> gemm W1 (regs); gemm W2; mask -> g_b2h ----------
__global__ void __launch_bounds__(NT)
K1(const float* __restrict__ x, const float* __restrict__ wdw) {
    extern __shared__ char sm[];
    char* W1h = sm;
    char* W1l = sm + WBYTES;
    char* W2h = sm + 2 * WBYTES;
    char* W2l = sm + 3 * WBYTES;
    char* A0  = sm + 4 * WBYTES;
    char* A1  = sm + 5 * WBYTES;
    float* taps = (float*)(sm + 6 * WBYTES);

    const int tid = threadIdx.x, lane = tid & 31, warp = tid >> 5;
    const int m0 = (warp & 3) * 32, c0w = (warp >> 2) * 32;
    const int g = lane >> 2, t = lane & 3;

    loadW(W1h, W1l, 0, tid);
    loadW(W2h, W2l, 1, tid);
    for (int e = tid; e < 3 * CCH; e += NT)
        taps[e] = wdw[(e & 127) * 9 + (e >> 7) * 3 + 1];

    const u32 a0s = smem_u32(A0), a1s = smem_u32(A1);
    const u32 w1hs = smem_u32(W1h), w1ls = smem_u32(W1l);
    const u32 w2hs = smem_u32(W2h), w2ls = smem_u32(W2l);

    for (int tile = blockIdx.x; tile < NTILES; tile += gridDim.x) {
        const int base = tile * TILE_M;
        fillA_dual(A0, A1, x, base, taps, tid);
        __syncthreads();

        float accT[8][4], accX[8][4];
        ZACC(accT); ZACC(accX);
        sweep(a0s, w1hs, w1ls, m0, c0w, lane, accT);
        sweep(a1s, w2hs, w2ls, m0, c0w, lane, accX);

        // b2 = mask(relu(accX) + relu(accT)) -> g_b2h (fp16)
#pragma unroll 1
        for (int f = 0; f < 8; f++) {
            const int mt = f >> 2, nt = f & 3;
            const int r0 = base + m0 + mt * 16 + g;
            const int c0 = c0w + nt * 8 + t * 2;
            float v00 = fmaxf(accX[f][0], 0.f) + fmaxf(accT[f][0], 0.f);
            float v01 = fmaxf(accX[f][1], 0.f) + fmaxf(accT[f][1], 0.f);
            float v10 = fmaxf(accX[f][2], 0.f) + fmaxf(accT[f][2], 0.f);
            float v11 = fmaxf(accX[f][3], 0.f) + fmaxf(accT[f][3], 0.f);
            u32 fc = (u32)c0 << 17;             // flat = col*131072 + row
            if (!keepbit(fc + (u32)r0))                    v00 = 0.f;
            if (!keepbit(fc + (1u << 17) + (u32)r0))       v01 = 0.f;
            if (!keepbit(fc + (u32)(r0 + 8)))              v10 = 0.f;
            if (!keepbit(fc + (1u << 17) + (u32)(r0 + 8))) v11 = 0.f;
            *(__half2*)(g_b2h + (size_t)r0 * CCH + c0) =
                __floats2half2_rn(v00, v01);
            *(__half2*)(g_b2h + (size_t)(r0 + 8) * CCH + c0) =
                __floats2half2_rn(v10, v11);
        }
        __syncthreads();   // A buffers reused next iteration
    }
}

// ---------------- K2: dw2(b2h) -> gemm W3 -> relu -> g_b2ph ------------------
__global__ void __launch_bounds__(NT)
K2(const float* __restrict__ wdw) {
    extern __shared__ char sm[];
    char* W3h = sm;
    char* W3l = sm + WBYTES;
    char* A   = sm + 2 * WBYTES;
    float* taps = (float*)(sm + 3 * WBYTES);

    const int tid = threadIdx.x, lane = tid & 31, warp = tid >> 5;
    const int m0 = (warp & 3) * 32, c0w = (warp >> 2) * 32;
    const int g = lane >> 2, t = lane & 3;

    loadW(W3h, W3l, 2, tid);
    for (int e = tid; e < 3 * CCH; e += NT)
        taps[e] = wdw[(e & 127) * 9 + (e >> 7) * 3 + 1];

    const u32 as = smem_u32(A);
    const u32 whs = smem_u32(W3h), wls = smem_u32(W3l);

    for (int tile = blockIdx.x; tile < NTILES; tile += gridDim.x) {
        const int base = tile * TILE_M;
        fillA_h(A, g_b2h, base, taps, tid);
        __syncthreads();

        float acc[8][4];
        ZACC(acc);
        sweep(as, whs, wls, m0, c0w, lane, acc);

#pragma unroll
        for (int f = 0; f < 8; f++) {
            const int mt = f >> 2, nt = f & 3;
            const int r0 = base + m0 + mt * 16 + g;
            const int c0 = c0w + nt * 8 + t * 2;
            *(__half2*)(g_b2ph + (size_t)r0 * CCH + c0) =
                __floats2half2_rn(fmaxf(acc[f][0], 0.f), fmaxf(acc[f][1], 0.f));
            *(__half2*)(g_b2ph + (size_t)(r0 + 8) * CCH + c0) =
                __floats2half2_rn(fmaxf(acc[f][2], 0.f), fmaxf(acc[f][3], 0.f));
        }
        __syncthreads();
    }
}

// ---------------- K3: out = relu(xh @ Wfa^T + b2ph @ Wfb^T), pipelined -------
__device__ __forceinline__ void prefK3(uint4 pfx[4], uint4 pfb[4],
                                       int base, int tid) {
#pragma unroll
    for (int c = 0; c < 4; c++) {
        int q = tid + c * NT;
        int m = q >> 4, k0 = (q & 15) << 3;
        size_t go = (size_t)(base + m) * CCH + k0;
        pfx[c] = *(const uint4*)(g_xh + go);
        pfb[c] = *(const uint4*)(g_b2ph + go);
    }
}

__global__ void __launch_bounds__(NT)
K3(float* __restrict__ out) {
    extern __shared__ char sm[];
    char* Wah = sm;
    char* Wal = sm + WBYTES;
    char* Wbh = sm + 2 * WBYTES;
    char* Wbl = sm + 3 * WBYTES;
    char* A0  = sm + 4 * WBYTES;
    char* A1  = sm + 5 * WBYTES;

    const int tid = threadIdx.x, lane = tid & 31, warp = tid >> 5;
    const int m0 = (warp & 3) * 32, c0w = (warp >> 2) * 32;
    const int g = lane >> 2, t = lane & 3;

    loadW(Wah, Wal, 3, tid);
    loadW(Wbh, Wbl, 4, tid);

    const u32 a0s = smem_u32(A0), a1s = smem_u32(A1);
    const u32 wahs = smem_u32(Wah), wals = smem_u32(Wal);
    const u32 wbhs = smem_u32(Wbh), wbls = smem_u32(Wbl);

    uint4 pfx[4], pfb[4];
    int tile = blockIdx.x;
    if (tile < NTILES) prefK3(pfx, pfb, tile * TILE_M, tid);

    for (; tile < NTILES; tile += gridDim.x) {
        // store prefetched tile to smem
#pragma unroll
        for (int c = 0; c < 4; c++) {
            int q = tid + c * NT;
            int m = q >> 4, k0 = (q & 15) << 3;
            u32 off = (u32)(m * PITCHB + k0) * 2;
            *(uint4*)(A0 + off) = pfx[c];
            *(uint4*)(A1 + off) = pfb[c];
        }
        __syncthreads();

        // issue next tile's loads; they fly during the sweeps below
        int ntile = tile + gridDim.x;
        if (ntile < NTILES) prefK3(pfx, pfb, ntile * TILE_M, tid);

        float acc[8][4];
        ZACC(acc);
        sweep(a0s, wahs, wals, m0, c0w, lane, acc);
        sweep(a1s, wbhs, wbls, m0, c0w, lane, acc);

        const int base = tile * TILE_M;
#pragma unroll
        for (int f = 0; f < 8; f++) {
            const int mt = f >> 2, nt = f & 3;
            const int r0 = base + m0 + mt * 16 + g;
            const int c0 = c0w + nt * 8 + t * 2;
            *(float2*)(out + (size_t)r0 * CCH + c0) =
                make_float2(fmaxf(acc[f][0], 0.f), fmaxf(acc[f][1], 0.f));
            *(float2*)(out + (size_t)(r0 + 8) * CCH + c0) =
                make_float2(fmaxf(acc[f][2], 0.f), fmaxf(acc[f][3], 0.f));
        }
        __syncthreads();
    }
}

// ---------------- launch ------------------------------------------------------
extern "C" void kernel_launch(void* const* d_in, const int* in_sizes, int n_in,
                              void* d_out, int out_size) {
    const float* x        = (const float*)d_in[0];
    const float* w_b1_dw  = (const float*)d_in[1];
    const float* w_b1_pw  = (const float*)d_in[2];
    const float* w_b2_1x1 = (const float*)d_in[3];
    const float* w_b2_dw  = (const float*)d_in[4];
    const float* w_b2_pw  = (const float*)d_in[5];
    const float* w_fusion = (const float*)d_in[6];
    float*       out      = (float*)d_out;

    cudaFuncSetAttribute(K1, cudaFuncAttributeMaxDynamicSharedMemorySize, SM1);
    cudaFuncSetAttribute(K2, cudaFuncAttributeMaxDynamicSharedMemorySize, SM2);
    cudaFuncSetAttribute(K3, cudaFuncAttributeMaxDynamicSharedMemorySize, SM3);

    kPrep<<<(5 * CCH * CCH + 255) / 256, 256>>>(w_b1_pw, w_b2_1x1, w_b2_pw, w_fusion);
    K1<<<GRID1, NT, SM1>>>(x, w_b1_dw);
    K2<<<GRID2, NT, SM2>>>(w_b2_dw);
    K3<<<GRID1, NT, SM3>>>(out);
}

// round 14
// speedup vs baseline: 1.6249x; 1.0673x over previous
#include <cuda_runtime.h>
#include <cuda_fp16.h>

// ----------------------------------------------------------------------------
// KB_Mapping_19361712570541 — HMMA fp16 2-term split, persistent CTAs,
// fp16 intermediates, prefetch pipelines, mask fused into MMA sweep.
//   K1: A1 = fp16(x) [prefetched, 1 pass]; A0 = relu(dw1(A1 smem));
//       t1 = relu(A0 @ W1^T) [compressed regs];
//       b2 = mask(relu(A1 @ W2^T) + t1) -> g_b2h; side-writes g_xh.
//   K2: b2p = relu(relu(dw2(b2h)) @ W3^T) -> g_b2ph
//   K3: out = relu(xh @ Wfa^T + b2ph @ Wfb^T)   (pipelined raw fp16 copies)
// GEMMs: A@W ~= Afp16 @ Whi + Afp16 @ Wlo  (W split ~22 mantissa bits).
// Warp map (16 warps, 4x4): rows (warp&3)*32..+32, cols (warp>>2)*32..+32.
// ----------------------------------------------------------------------------

#define NTOK   131072
#define CCH    128
#define TILE_M 128
#define NTILES (NTOK / TILE_M)   // 1024
#define NT     512
#define PITCHB 136               // fp16 smem pitch (ldmatrix conflict-free)
#define WBYTES (CCH * PITCHB * 2)   // 34816 bytes per fp16 matrix tile
#define GRID1  148
#define GRID2  296

typedef unsigned int u32;

// ---------------- device scratch ---------------------------------------------
__device__ __half g_xh  [(size_t)NTOK * CCH];   // fp16(x), written by K1
__device__ __half g_b2h [(size_t)NTOK * CCH];   // fp16(b2)
__device__ __half g_b2ph[(size_t)NTOK * CCH];   // fp16(b2p)
__device__ __half g_whi[5][CCH * CCH];          // row-major [o][k] hi part
__device__ __half g_wlo[5][CCH * CCH];          // lo part (residual)

// ---------------- PTX helpers -------------------------------------------------
__device__ __forceinline__ u32 smem_u32(const void* p) {
    u32 a;
    asm("{ .reg .u64 t; cvta.to.shared.u64 t, %1; cvt.u32.u64 %0, t; }"
        : "=r"(a) : "l"(p));
    return a;
}
#define LDM4(r, a)                                                          \
    asm volatile("ldmatrix.sync.aligned.m8n8.x4.shared.b16 {%0,%1,%2,%3}, [%4];" \
                 : "=r"((r)[0]), "=r"((r)[1]), "=r"((r)[2]), "=r"((r)[3])   \
                 : "r"(a))
#define MMA(c, a, b0, b1)                                                   \
    asm volatile("mma.sync.aligned.m16n8k16.row.col.f32.f16.f16.f32 "       \
                 "{%0,%1,%2,%3}, {%4,%5,%6,%7}, {%8,%9}, {%0,%1,%2,%3};"    \
                 : "+f"((c)[0]), "+f"((c)[1]), "+f"((c)[2]), "+f"((c)[3])   \
                 : "r"((a)[0]), "r"((a)[1]), "r"((a)[2]), "r"((a)[3]),      \
                   "r"(b0), "r"(b1))

// ---------------- threefry-2x32 partitionable keep-bit (validated R5) ---------
__device__ __forceinline__ u32 rotl32(u32 x, int r) { return __funnelshift_l(x, x, r); }
__device__ __forceinline__ u32 keepbit(u32 fidx) {
    const u32 K0 = 0u, K1 = 42u, K2 = 0u ^ 42u ^ 0x1BD11BDAu;
    u32 x0 = 0u + K0;      // counts_hi = 0
    u32 x1 = fidx + K1;    // counts_lo = f
#define TF_R4(a,b,c,d)                               \
    x0 += x1; x1 = rotl32(x1,(a)); x1 ^= x0;         \
    x0 += x1; x1 = rotl32(x1,(b)); x1 ^= x0;         \
    x0 += x1; x1 = rotl32(x1,(c)); x1 ^= x0;         \
    x0 += x1; x1 = rotl32(x1,(d)); x1 ^= x0;
    TF_R4(13,15,26, 6);  x0 += K1; x1 += K2 + 1u;
    TF_R4(17,29,16,24);  x0 += K2; x1 += K0 + 2u;
    TF_R4(13,15,26, 6);  x0 += K0; x1 += K1 + 3u;
    TF_R4(17,29,16,24);  x0 += K1; x1 += K2 + 4u;
    TF_R4(13,15,26, 6);  x0 += K2; x1 += K0 + 5u;
#undef TF_R4
    return (~(x0 ^ x1)) >> 31;   // 1 = keep (MSB of xor-fold == 0)
}

// ---------------- weight prep: fp16 hi/lo split, row-major [o][k] ------------
__global__ void kPrep(const float* __restrict__ w1, const float* __restrict__ w2,
                      const float* __restrict__ w3, const float* __restrict__ wf) {
    int e = blockIdx.x * blockDim.x + threadIdx.x;
    if (e >= 5 * CCH * CCH) return;
    int mat = e >> 14, idx = e & 16383, o = idx >> 7, k = idx & 127;
    float v;
    if      (mat == 0) v = w1[idx];              // w_b1_pw
    else if (mat == 1) v = w2[idx];              // w_b2_1x1
    else if (mat == 2) v = w3[idx];              // w_b2_pw
    else if (mat == 3) v = wf[o * 256 + k];      // w_fusion[:, :128]
    else               v = wf[o * 256 + 128 + k];// w_fusion[:, 128:]
    __half h = __float2half_rn(v);
    __half l = __float2half_rn(v - __half2float(h));
    g_whi[mat][idx] = h;
    g_wlo[mat][idx] = l;
}

// ---------------- tile helpers ------------------------------------------------
__device__ __forceinline__ void load8(float v[8], const float* __restrict__ p,
                                      long row, int k0) {
    if ((unsigned long)row < (unsigned long)NTOK) {
        float4 a = *(const float4*)(p + row * CCH + k0);
        float4 b = *(const float4*)(p + row * CCH + k0 + 4);
        v[0]=a.x; v[1]=a.y; v[2]=a.z; v[3]=a.w;
        v[4]=b.x; v[5]=b.y; v[6]=b.z; v[7]=b.w;
    } else {
#pragma unroll
        for (int j = 0; j < 8; j++) v[j] = 0.f;
    }
}
__device__ __forceinline__ void load8h(float v[8], const __half* __restrict__ p,
                                       long row, int k0) {
    if ((unsigned long)row < (unsigned long)NTOK) {
        uint4 r = *(const uint4*)(p + row * CCH + k0);
        const __half2* h2 = (const __half2*)&r;
#pragma unroll
        for (int j = 0; j < 4; j++) {
            float2 f = __half22float2(h2[j]);
            v[2 * j] = f.x; v[2 * j + 1] = f.y;
        }
    } else {
#pragma unroll
        for (int j = 0; j < 8; j++) v[j] = 0.f;
    }
}
__device__ __forceinline__ void unpack8s(float v[8], const char* p) {
    uint4 r = *(const uint4*)p;
    const __half2* h2 = (const __half2*)&r;
#pragma unroll
    for (int j = 0; j < 4; j++) {
        float2 f = __half22float2(h2[j]);
        v[2 * j] = f.x; v[2 * j + 1] = f.y;
    }
}
__device__ __forceinline__ uint4 pack8h(const float v[8]) {
    uint4 r;
    __half2* h2 = (__half2*)&r;
#pragma unroll
    for (int j = 0; j < 4; j++)
        h2[j] = __floats2half2_rn(v[2 * j], v[2 * j + 1]);
    return r;
}

// Copy one pre-split weight matrix into pitched smem (hi+lo).
__device__ __forceinline__ void loadW(char* hd, char* ld, int mat, int tid) {
    const uint4* sh = (const uint4*)g_whi[mat];
    const uint4* sl = (const uint4*)g_wlo[mat];
#pragma unroll
    for (int q = tid; q < 2048; q += NT) {             // 16 uint4 per row
        int n = q >> 4, k0 = (q & 15) << 3;
        u32 doff = (u32)(n * PITCHB + k0) * 2;
        *(uint4*)(hd + doff) = sh[q];
        *(uint4*)(ld + doff) = sl[q];
    }
}

// K2 fill from fp16 source with fused dw + relu.
__device__ __forceinline__ void fillA_h(char* A, const __half* __restrict__ src,
                                        int base, const float* taps, int tid) {
#pragma unroll 1
    for (int q = tid; q < 2048; q += NT) {
        int m = q >> 4, k0 = (q & 15) << 3;
        long gr = (long)base + m;
        float a[8], b[8], c[8], v[8];
        load8h(a, src, gr - 1, k0);
        load8h(b, src, gr,     k0);
        load8h(c, src, gr + 1, k0);
#pragma unroll
        for (int j = 0; j < 8; j++) {
            int ch = k0 + j;
            v[j] = fmaxf(taps[ch] * a[j] + taps[CCH + ch] * b[j]
                         + taps[2 * CCH + ch] * c[j], 0.f);
        }
        *(uint4*)(A + (u32)(m * PITCHB + k0) * 2) = pack8h(v);
    }
}

// 2-term split GEMM sweep: acc += A @ Whi + A @ Wlo.
// Warp: rows [m0, m0+32) (2 m-tiles) x cols [c0w, c0w+32) (2 n-pairs).
__device__ __forceinline__ void sweep(u32 as, u32 whs, u32 wls,
                                      int m0, int c0w, int lane, float (*acc)[4]) {
    const u32 arow  = (u32)(m0 + (lane & 7) + (lane & 8));
    const u32 acolb = (u32)((lane & 16) >> 1);             // 0 or 8
    const u32 brow0 = (u32)((lane & 7) + ((lane & 16) >> 1));
    const u32 astride = (u32)(16 * PITCHB * 2);            // 16 rows of A
#pragma unroll 2
    for (int k = 0; k < 8; k++) {
        u32 aoff = (arow * PITCHB + (u32)k * 16 + acolb) * 2;
        u32 a0[4], a1[4];
        LDM4(a0, as + aoff);
        LDM4(a1, as + aoff + astride);
        u32 bcol = ((u32)k * 16 + (u32)(lane & 8)) * 2;
        u32 boff0 = ((u32)c0w        + brow0) * (PITCHB * 2) + bcol;
        u32 boff1 = ((u32)(c0w + 16) + brow0) * (PITCHB * 2) + bcol;
        u32 bh0[4], bl0[4], bh1[4], bl1[4];
        LDM4(bh0, whs + boff0);
        LDM4(bl0, wls + boff0);
        LDM4(bh1, whs + boff1);
        LDM4(bl1, wls + boff1);
        MMA(acc[0], a0, bh0[0], bh0[1]);
        MMA(acc[0], a0, bl0[0], bl0[1]);
        MMA(acc[1], a0, bh0[2], bh0[3]);
        MMA(acc[1], a0, bl0[2], bl0[3]);
        MMA(acc[2], a0, bh1[0], bh1[1]);
        MMA(acc[2], a0, bl1[0], bl1[1]);
        MMA(acc[3], a0, bh1[2], bh1[3]);
        MMA(acc[3], a0, bl1[2], bl1[3]);
        MMA(acc[4], a1, bh0[0], bh0[1]);
        MMA(acc[4], a1, bl0[0], bl0[1]);
        MMA(acc[5], a1, bh0[2], bh0[3]);
        MMA(acc[5], a1, bl0[2], bl0[3]);
        MMA(acc[6], a1, bh1[0], bh1[1]);
        MMA(acc[6], a1, bl1[0], bl1[1]);
        MMA(acc[7], a1, bh1[2], bh1[3]);
        MMA(acc[7], a1, bl1[2], bl1[3]);
    }
}

// Sweep variant with threefry mask fused into the k-loop: iteration k also
// computes the 4 keep-bits of output fragment k (rides idle issue slots).
__device__ __forceinline__ void sweep_mask(u32 as, u32 whs, u32 wls,
                                           int m0, int c0w, int lane,
                                           int base, int g, int t,
                                           float (*acc)[4], u32* mbout) {
    const u32 arow  = (u32)(m0 + (lane & 7) + (lane & 8));
    const u32 acolb = (u32)((lane & 16) >> 1);
    const u32 brow0 = (u32)((lane & 7) + ((lane & 16) >> 1));
    const u32 astride = (u32)(16 * PITCHB * 2);
    u32 mb = 0;
#pragma unroll 2
    for (int k = 0; k < 8; k++) {
        u32 aoff = (arow * PITCHB + (u32)k * 16 + acolb) * 2;
        u32 a0[4], a1[4];
        LDM4(a0, as + aoff);
        LDM4(a1, as + aoff + astride);
        u32 bcol = ((u32)k * 16 + (u32)(lane & 8)) * 2;
        u32 boff0 = ((u32)c0w        + brow0) * (PITCHB * 2) + bcol;
        u32 boff1 = ((u32)(c0w + 16) + brow0) * (PITCHB * 2) + bcol;
        u32 bh0[4], bl0[4], bh1[4], bl1[4];
        LDM4(bh0, whs + boff0);
        LDM4(bl0, wls + boff0);
        LDM4(bh1, whs + boff1);
        LDM4(bl1, wls + boff1);
        MMA(acc[0], a0, bh0[0], bh0[1]);
        MMA(acc[0], a0, bl0[0], bl0[1]);
        MMA(acc[1], a0, bh0[2], bh0[3]);
        MMA(acc[1], a0, bl0[2], bl0[3]);
        MMA(acc[2], a0, bh1[0], bh1[1]);
        MMA(acc[2], a0, bl1[0], bl1[1]);
        MMA(acc[3], a0, bh1[2], bh1[3]);
        MMA(acc[3], a0, bl1[2], bl1[3]);
        MMA(acc[4], a1, bh0[0], bh0[1]);
        MMA(acc[4], a1, bl0[0], bl0[1]);
        MMA(acc[5], a1, bh0[2], bh0[3]);
        MMA(acc[5], a1, bl0[2], bl0[3]);
        MMA(acc[6], a1, bh1[0], bh1[1]);
        MMA(acc[6], a1, bl1[0], bl1[1]);
        MMA(acc[7], a1, bh1[2], bh1[3]);
        MMA(acc[7], a1, bl1[2], bl1[3]);
        // fragment k mask bits: flat index = col*131072 + row
        {
            u32 r0 = (u32)(base + m0 + (k >> 2) * 16 + g);
            u32 c0 = (u32)(c0w + (k & 3) * 8 + t * 2);
            u32 fb = (c0 << 17) + r0;
            mb |= keepbit(fb)                    << (k * 4 + 0);
            mb |= keepbit(fb + (1u << 17))       << (k * 4 + 1);
            mb |= keepbit(fb + 8u)               << (k * 4 + 2);
            mb |= keepbit(fb + (1u << 17) + 8u)  << (k * 4 + 3);
        }
    }
    *mbout = mb;
}

#define ZACC(a) { _Pragma("unroll") for (int _i = 0; _i < 8; _i++) \
                  _Pragma("unroll") for (int _j = 0; _j < 4; _j++) (a)[_i][_j] = 0.f; }

// Shared-memory sizes
#define SM1 (6 * WBYTES + 3 * CCH * 4 + 4 * PITCHB)  // W1h/l W2h/l A0 A1 taps halo
#define SM2 (3 * WBYTES + 3 * CCH * 4)               // W3 h/l, A, taps
#define SM3 (6 * WBYTES)                             // Wfa h/l, Wfb h/l, A0, A1

// ---------------- K1 ----------------------------------------------------------
__device__ __forceinline__ void prefK1(uint4 pf[4][2], const float* __restrict__ x,
                                       int base, int tid) {
#pragma unroll
    for (int c = 0; c < 4; c++) {
        int q = tid + c * NT;
        int m = q >> 4, k0 = (q & 15) << 3;
        const float* p = x + (size_t)(base + m) * CCH + k0;
        pf[c][0] = *(const uint4*)p;
        pf[c][1] = *(const uint4*)(p + 4);
    }
}

__global__ void __launch_bounds__(NT)
K1(const float* __restrict__ x, const float* __restrict__ wdw) {
    extern __shared__ char sm[];
    char* W1h = sm;
    char* W1l = sm + WBYTES;
    char* W2h = sm + 2 * WBYTES;
    char* W2l = sm + 3 * WBYTES;
    char* A0  = sm + 4 * WBYTES;
    char* A1  = sm + 5 * WBYTES;
    float* taps = (float*)(sm + 6 * WBYTES);
    char* haloH = sm + 6 * WBYTES + 3 * CCH * 4;   // 2 rows x PITCHB fp16

    const int tid = threadIdx.x, lane = tid & 31, warp = tid >> 5;
    const int m0 = (warp & 3) * 32, c0w = (warp >> 2) * 32;
    const int g = lane >> 2, t = lane & 3;

    loadW(W1h, W1l, 0, tid);
    loadW(W2h, W2l, 1, tid);
    for (int e = tid; e < 3 * CCH; e += NT)
        taps[e] = wdw[(e & 127) * 9 + (e >> 7) * 3 + 1];

    const u32 a0s = smem_u32(A0), a1s = smem_u32(A1);
    const u32 w1hs = smem_u32(W1h), w1ls = smem_u32(W1l);
    const u32 w2hs = smem_u32(W2h), w2ls = smem_u32(W2l);

    uint4 pf[4][2];
    int tile = blockIdx.x;
    if (tile < NTILES) prefK1(pf, x, tile * TILE_M, tid);

    for (; tile < NTILES; tile += gridDim.x) {
        const int base = tile * TILE_M;

        // stage A1 = fp16(x) from prefetch; side-write g_xh; halo rows
#pragma unroll
        for (int c = 0; c < 4; c++) {
            int q = tid + c * NT;
            int m = q >> 4, k0 = (q & 15) << 3;
            float v[8];
            const float* f = (const float*)pf[c];
#pragma unroll
            for (int j = 0; j < 8; j++) v[j] = f[j];
            uint4 hx = pack8h(v);
            *(uint4*)(A1 + (u32)(m * PITCHB + k0) * 2) = hx;
            *(uint4*)(g_xh + (size_t)(base + m) * CCH + k0) = hx;
        }
        if (tid < 32) {
            int sel = tid >> 4;              // 0: base-1, 1: base+TILE_M
            int k0 = (tid & 15) << 3;
            long gr = sel ? (long)base + TILE_M : (long)base - 1;
            float v[8];
            load8(v, x, gr, k0);
            *(uint4*)(haloH + (u32)(sel * PITCHB + k0) * 2) = pack8h(v);
        }
        __syncthreads();

        // A0 = fp16(relu(dw1(A1)))  (all-smem reads)
#pragma unroll 1
        for (int c = 0; c < 4; c++) {
            int q = tid + c * NT;
            int m = q >> 4, k0 = (q & 15) << 3;
            const char* rm = (m == 0) ? haloH + (u32)k0 * 2
                                      : A1 + (u32)((m - 1) * PITCHB + k0) * 2;
            const char* rp = (m == TILE_M - 1)
                                      ? haloH + (u32)(PITCHB + k0) * 2
                                      : A1 + (u32)((m + 1) * PITCHB + k0) * 2;
            float a[8], b[8], cc[8], v[8];
            unpack8s(a, rm);
            unpack8s(b, A1 + (u32)(m * PITCHB + k0) * 2);
            unpack8s(cc, rp);
#pragma unroll
            for (int j = 0; j < 8; j++) {
                int ch = k0 + j;
                v[j] = fmaxf(taps[ch] * a[j] + taps[CCH + ch] * b[j]
                             + taps[2 * CCH + ch] * cc[j], 0.f);
            }
            *(uint4*)(A0 + (u32)(m * PITCHB + k0) * 2) = pack8h(v);
        }
        __syncthreads();

        // issue next tile's x loads; they fly during both sweeps
        int ntile = tile + gridDim.x;
        if (ntile < NTILES) prefK1(pf, x, ntile * TILE_M, tid);

        float acc[8][4];
        ZACC(acc);
        sweep(a0s, w1hs, w1ls, m0, c0w, lane, acc);   // t1 = A0 @ W1^T

        // compress relu(t1) to fp16 regs (b2 is stored fp16 anyway)
        u32 t1h[16];
#pragma unroll
        for (int f = 0; f < 8; f++) {
            __half2 lo = __floats2half2_rn(fmaxf(acc[f][0], 0.f), fmaxf(acc[f][1], 0.f));
            __half2 hi = __floats2half2_rn(fmaxf(acc[f][2], 0.f), fmaxf(acc[f][3], 0.f));
            t1h[2 * f]     = *(u32*)&lo;
            t1h[2 * f + 1] = *(u32*)&hi;
        }

        ZACC(acc);
        u32 mb;
        sweep_mask(a1s, w2hs, w2ls, m0, c0w, lane, base, g, t, acc, &mb);

        // b2 = mask(relu(accX) + t1) -> g_b2h (fp16)
#pragma unroll
        for (int f = 0; f < 8; f++) {
            const int mt = f >> 2, nt = f & 3;
            const int r0 = base + m0 + mt * 16 + g;
            const int c0 = c0w + nt * 8 + t * 2;
            float2 tl = __half22float2(*(__half2*)&t1h[2 * f]);
            float2 th = __half22float2(*(__half2*)&t1h[2 * f + 1]);
            float v00 = fmaxf(acc[f][0], 0.f) + tl.x;
            float v01 = fmaxf(acc[f][1], 0.f) + tl.y;
            float v10 = fmaxf(acc[f][2], 0.f) + th.x;
            float v11 = fmaxf(acc[f][3], 0.f) + th.y;
            if (!((mb >> (f * 4 + 0)) & 1u)) v00 = 0.f;
            if (!((mb >> (f * 4 + 1)) & 1u)) v01 = 0.f;
            if (!((mb >> (f * 4 + 2)) & 1u)) v10 = 0.f;
            if (!((mb >> (f * 4 + 3)) & 1u)) v11 = 0.f;
            *(__half2*)(g_b2h + (size_t)r0 * CCH + c0) = __floats2half2_rn(v00, v01);
            *(__half2*)(g_b2h + (size_t)(r0 + 8) * CCH + c0) = __floats2half2_rn(v10, v11);
        }
        __syncthreads();   // A buffers reused next iteration
    }
}

// ---------------- K2: dw2(b2h) -> gemm W3 -> relu -> g_b2ph ------------------
__global__ void __launch_bounds__(NT)
K2(const float* __restrict__ wdw) {
    extern __shared__ char sm[];
    char* W3h = sm;
    char* W3l = sm + WBYTES;
    char* A   = sm + 2 * WBYTES;
    float* taps = (float*)(sm + 3 * WBYTES);

    const int tid = threadIdx.x, lane = tid & 31, warp = tid >> 5;
    const int m0 = (warp & 3) * 32, c0w = (warp >> 2) * 32;
    const int g = lane >> 2, t = lane & 3;

    loadW(W3h, W3l, 2, tid);
    for (int e = tid; e < 3 * CCH; e += NT)
        taps[e] = wdw[(e & 127) * 9 + (e >> 7) * 3 + 1];

    const u32 as = smem_u32(A);
    const u32 whs = smem_u32(W3h), wls = smem_u32(W3l);

    for (int tile = blockIdx.x; tile < NTILES; tile += gridDim.x) {
        const int base = tile * TILE_M;
        fillA_h(A, g_b2h, base, taps, tid);
        __syncthreads();

        float acc[8][4];
        ZACC(acc);
        sweep(as, whs, wls, m0, c0w, lane, acc);

#pragma unroll
        for (int f = 0; f < 8; f++) {
            const int mt = f >> 2, nt = f & 3;
            const int r0 = base + m0 + mt * 16 + g;
            const int c0 = c0w + nt * 8 + t * 2;
            *(__half2*)(g_b2ph + (size_t)r0 * CCH + c0) =
                __floats2half2_rn(fmaxf(acc[f][0], 0.f), fmaxf(acc[f][1], 0.f));
            *(__half2*)(g_b2ph + (size_t)(r0 + 8) * CCH + c0) =
                __floats2half2_rn(fmaxf(acc[f][2], 0.f), fmaxf(acc[f][3], 0.f));
        }
        __syncthreads();
    }
}

// ---------------- K3: out = relu(xh @ Wfa^T + b2ph @ Wfb^T), pipelined -------
__device__ __forceinline__ void prefK3(uint4 pfx[4], uint4 pfb[4],
                                       int base, int tid) {
#pragma unroll
    for (int c = 0; c < 4; c++) {
        int q = tid + c * NT;
        int m = q >> 4, k0 = (q & 15) << 3;
        size_t go = (size_t)(base + m) * CCH + k0;
        pfx[c] = *(const uint4*)(g_xh + go);
        pfb[c] = *(const uint4*)(g_b2ph + go);
    }
}

__global__ void __launch_bounds__(NT)
K3(float* __restrict__ out) {
    extern __shared__ char sm[];
    char* Wah = sm;
    char* Wal = sm + WBYTES;
    char* Wbh = sm + 2 * WBYTES;
    char* Wbl = sm + 3 * WBYTES;
    char* A0  = sm + 4 * WBYTES;
    char* A1  = sm + 5 * WBYTES;

    const int tid = threadIdx.x, lane = tid & 31, warp = tid >> 5;
    const int m0 = (warp & 3) * 32, c0w = (warp >> 2) * 32;
    const int g = lane >> 2, t = lane & 3;

    loadW(Wah, Wal, 3, tid);
    loadW(Wbh, Wbl, 4, tid);

    const u32 a0s = smem_u32(A0), a1s = smem_u32(A1);
    const u32 wahs = smem_u32(Wah), wals = smem_u32(Wal);
    const u32 wbhs = smem_u32(Wbh), wbls = smem_u32(Wbl);

    uint4 pfx[4], pfb[4];
    int tile = blockIdx.x;
    if (tile < NTILES) prefK3(pfx, pfb, tile * TILE_M, tid);

    for (; tile < NTILES; tile += gridDim.x) {
#pragma unroll
        for (int c = 0; c < 4; c++) {
            int q = tid + c * NT;
            int m = q >> 4, k0 = (q & 15) << 3;
            u32 off = (u32)(m * PITCHB + k0) * 2;
            *(uint4*)(A0 + off) = pfx[c];
            *(uint4*)(A1 + off) = pfb[c];
        }
        __syncthreads();

        int ntile = tile + gridDim.x;
        if (ntile < NTILES) prefK3(pfx, pfb, ntile * TILE_M, tid);

        float acc[8][4];
        ZACC(acc);
        sweep(a0s, wahs, wals, m0, c0w, lane, acc);
        sweep(a1s, wbhs, wbls, m0, c0w, lane, acc);

        const int base = tile * TILE_M;
#pragma unroll
        for (int f = 0; f < 8; f++) {
            const int mt = f >> 2, nt = f & 3;
            const int r0 = base + m0 + mt * 16 + g;
            const int c0 = c0w + nt * 8 + t * 2;
            *(float2*)(out + (size_t)r0 * CCH + c0) =
                make_float2(fmaxf(acc[f][0], 0.f), fmaxf(acc[f][1], 0.f));
            *(float2*)(out + (size_t)(r0 + 8) * CCH + c0) =
                make_float2(fmaxf(acc[f][2], 0.f), fmaxf(acc[f][3], 0.f));
        }
        __syncthreads();
    }
}

// ---------------- launch ------------------------------------------------------
extern "C" void kernel_launch(void* const* d_in, const int* in_sizes, int n_in,
                              void* d_out, int out_size) {
    const float* x        = (const float*)d_in[0];
    const float* w_b1_dw  = (const float*)d_in[1];
    const float* w_b1_pw  = (const float*)d_in[2];
    const float* w_b2_1x1 = (const float*)d_in[3];
    const float* w_b2_dw  = (const float*)d_in[4];
    const float* w_b2_pw  = (const float*)d_in[5];
    const float* w_fusion = (const float*)d_in[6];
    float*       out      = (float*)d_out;

    cudaFuncSetAttribute(K1, cudaFuncAttributeMaxDynamicSharedMemorySize, SM1);
    cudaFuncSetAttribute(K2, cudaFuncAttributeMaxDynamicSharedMemorySize, SM2);
    cudaFuncSetAttribute(K3, cudaFuncAttributeMaxDynamicSharedMemorySize, SM3);

    kPrep<<<(5 * CCH * CCH + 255) / 256, 256>>>(w_b1_pw, w_b2_1x1, w_b2_pw, w_fusion);
    K1<<<GRID1, NT, SM1>>>(x, w_b1_dw);
    K2<<<GRID2, NT, SM2>>>(w_b2_dw);
    K3<<<GRID1, NT, SM3>>>(out);
}